// round 14
// baseline (speedup 1.0000x reference)
#include <cuda_runtime.h>
#include <cuda_fp16.h>

#define NN   50000
#define NE   800000
#define NB   4
#define IND  64
#define HIDD 64
#define OUTD 32
#define NROWS (NN * NB)          // 200000

typedef unsigned long long u64;
typedef unsigned int u32;

// ---------------- scratch (static device globals; zero-init at load) ----------------
__device__ __align__(16) __half g_z1[(size_t)NN * NB * HIDD];  // fp16 (h@W1)*snorm, node-major [q=n*4+b][64]
__device__ __align__(16) float  g_agg1[(size_t)NN * NB * HIDD];
__device__ __align__(16) __half g_z2[(size_t)NN * NB * OUTD];  // fp16 snorm*(relu(agg*dn+b1)@W2)
__device__ float g_snorm[NN];
__device__ float g_dnorm[NN];
__device__ int   g_odeg[NN];     // zeroed at tail of k_agg2 each call
__device__ int   g_ideg[NN];     // ditto
__device__ int   g_coff[NN];
__device__ int   g_cur [NN];
__device__ int   g_esrc[NE];
__device__ volatile u64 g_pub[128];   // scan block publications: bit63=ready | total

// ---------------- tf32 helpers ----------------
__device__ __forceinline__ u32 tf32(float f) {
    u32 r; asm("cvt.rna.tf32.f32 %0, %1;" : "=r"(r) : "f"(f)); return r;
}
__device__ __forceinline__ void mma_tf32(float* c, u32 a0, u32 a1, u32 a2, u32 a3,
                                         u32 b0, u32 b1) {
    asm volatile(
        "mma.sync.aligned.m16n8k8.row.col.f32.tf32.tf32.f32 "
        "{%0,%1,%2,%3}, {%4,%5,%6,%7}, {%8,%9}, {%0,%1,%2,%3};"
        : "+f"(c[0]), "+f"(c[1]), "+f"(c[2]), "+f"(c[3])
        : "r"(a0), "r"(a1), "r"(a2), "r"(a3), "r"(b0), "r"(b1));
}

// ---------------- degree count (+ reset scan publications) ----------------
__global__ void k_deg(const int* __restrict__ src, const int* __restrict__ dst) {
    int i = blockIdx.x * blockDim.x + threadIdx.x;
    if (blockIdx.x == 0 && threadIdx.x < 128) g_pub[threadIdx.x] = 0ull;
    int stride = gridDim.x * blockDim.x;
    for (int e = i; e < NE; e += stride) {
        atomicAdd(&g_odeg[__ldg(src + e)], 1);
        atomicAdd(&g_ideg[__ldg(dst + e)], 1);
    }
}

// ---------------- single-pass scan + norms ----------------
#define SCAN_BLK 512
#define N_SCAN_BLKS ((NN + SCAN_BLK - 1) / SCAN_BLK)   // 98

__global__ void __launch_bounds__(SCAN_BLK) k_scanall() {
    __shared__ int ws[16];
    __shared__ int s_base;
    int t = threadIdx.x;
    int bid = blockIdx.x;
    int g = bid * SCAN_BLK + t;
    int ideg = (g < NN) ? g_ideg[g] : 0;

    int x = ideg;
    #pragma unroll
    for (int o = 1; o < 32; o <<= 1) {
        int y = __shfl_up_sync(0xffffffffu, x, o);
        if ((t & 31) >= o) x += y;
    }
    if ((t & 31) == 31) ws[t >> 5] = x;
    __syncthreads();
    if (t < 32) {
        int s = (t < 16) ? ws[t] : 0;
        #pragma unroll
        for (int o = 1; o < 16; o <<= 1) {
            int y = __shfl_up_sync(0xffffffffu, s, o);
            if (t >= o) s += y;
        }
        if (t < 16) ws[t] = s;
    }
    __syncthreads();
    int wbase = (t >> 5) ? ws[(t >> 5) - 1] : 0;
    int incl = x + wbase;

    if (t == SCAN_BLK - 1)
        g_pub[bid] = (1ull << 63) | (u64)(unsigned)incl;

    if (t < 32) {
        int sum = 0;
        for (int j = t; j < bid; j += 32) {
            u64 p;
            do { p = g_pub[j]; } while (!(p >> 63));
            sum += (int)(unsigned)p;
        }
        #pragma unroll
        for (int o = 16; o > 0; o >>= 1)
            sum += __shfl_xor_sync(0xffffffffu, sum, o);
        if (t == 0) s_base = sum;
    }
    __syncthreads();

    if (g < NN) {
        int ex = s_base + incl - ideg;
        g_coff[g] = ex;
        g_cur[g]  = ex;
        g_snorm[g] = rsqrtf((float)max(g_odeg[g], 1));
        g_dnorm[g] = rsqrtf((float)max(ideg, 1));
    }
}

__global__ void k_fill(const int* __restrict__ src, const int* __restrict__ dst) {
    int i = blockIdx.x * blockDim.x + threadIdx.x;
    int stride = gridDim.x * blockDim.x;
    for (int e = i; e < NE; e += stride) {
        int d = __ldg(dst + e);
        int pos = atomicAdd(&g_cur[d], 1);
        g_esrc[pos] = __ldg(src + e);
    }
}

// ================= tensor-core GEMM 1 (B fragments packed for LDS.128) =================
// sBf layout: uint4 per (kt, nt-pair p, lane): [((kt*4+p)*32 + lane)*4 + j]
//   j = (nt&1)*2 + i  (i = k-half index)
__global__ void __launch_bounds__(256) k_gemm1(const float* __restrict__ h,
                                               const float* __restrict__ W1) {
    __shared__ u32 sA[128 * 64];      // 32 KB
    __shared__ u32 sBf[8 * 4 * 32 * 4]; // 16 KB
    int tid = threadIdx.x;
    int lane = tid & 31;
    int w = tid >> 5;
    int row0 = blockIdx.x * 128;

    #pragma unroll
    for (int idx = tid; idx < IND * HIDD; idx += 256) {
        int k = idx >> 6, n = idx & 63;
        int kt = k >> 3, kr = k & 7;
        int i = kr >> 2;
        int fl = ((n & 7) << 2) | (kr & 3);
        int nt = n >> 3;
        int p = nt >> 1;
        int j = ((nt & 1) << 1) | i;
        sBf[(((kt * 4 + p) * 32) + fl) * 4 + j] = tf32(__ldg(W1 + idx));
    }
    #pragma unroll
    for (int it = 0; it < 8; it++) {
        int idx = tid + it * 256;        // 0..2047
        int r_l = idx >> 4;              // 0..127
        int kq  = idx & 15;              // float4 col
        int row = row0 + r_l;
        float4 v = make_float4(0.f, 0.f, 0.f, 0.f);
        if (row < NROWS) v = __ldg((const float4*)(h + (size_t)row * IND + kq * 4));
        int cc = (kq * 4) ^ ((r_l & 7) * 4);
        uint4 sv = make_uint4(tf32(v.x), tf32(v.y), tf32(v.z), tf32(v.w));
        *(uint4*)&sA[r_l * 64 + cc] = sv;
    }
    __syncthreads();

    float acc[8][4];
    #pragma unroll
    for (int nt = 0; nt < 8; nt++)
        #pragma unroll
        for (int j = 0; j < 4; j++) acc[nt][j] = 0.f;

    int rloc = w * 16 + (lane >> 2);
    const u32* rowp = sA + rloc * 64;
    const uint4* bq = (const uint4*)sBf;
    #pragma unroll
    for (int kt = 0; kt < 8; kt++) {
        int col0 = (kt * 8 + (lane & 3)) ^ (((lane >> 2) & 7) * 4);
        u32 a0 = rowp[col0];
        u32 a2 = rowp[col0 ^ 4];
        u32 a1 = rowp[col0 + 8 * 64];
        u32 a3 = rowp[(col0 ^ 4) + 8 * 64];
        #pragma unroll
        for (int p = 0; p < 4; p++) {
            uint4 b = bq[(kt * 4 + p) * 32 + lane];
            mma_tf32(acc[2 * p],     a0, a1, a2, a3, b.x, b.y);
            mma_tf32(acc[2 * p + 1], a0, a1, a2, a3, b.z, b.w);
        }
    }

    int r0 = row0 + rloc;
    int r1 = r0 + 8;
    int colb = (lane & 3) * 2;
    if (r0 < NROWS) {
        int b_ = r0 / NN, n_ = r0 - b_ * NN;
        float sc = g_snorm[n_];
        size_t base = ((size_t)n_ * NB + b_) * HIDD;
        #pragma unroll
        for (int nt = 0; nt < 8; nt++) {
            __half2 hv = __floats2half2_rn(sc * acc[nt][0], sc * acc[nt][1]);
            *(__half2*)(g_z1 + base + nt * 8 + colb) = hv;
        }
    }
    if (r1 < NROWS) {
        int b_ = r1 / NN, n_ = r1 - b_ * NN;
        float sc = g_snorm[n_];
        size_t base = ((size_t)n_ * NB + b_) * HIDD;
        #pragma unroll
        for (int nt = 0; nt < 8; nt++) {
            __half2 hv = __floats2half2_rn(sc * acc[nt][2], sc * acc[nt][3]);
            *(__half2*)(g_z1 + base + nt * 8 + colb) = hv;
        }
    }
}

// ---------------- gather layer 1: 8-wide batches, fp16 tree, fp32 accumulate ----------------
__global__ void __launch_bounds__(256) k_agg1() {
    int lane = threadIdx.x & 31;
    int n = blockIdx.x * 8 + (threadIdx.x >> 5);
    if (n >= NN) return;
    int beg = g_coff[n];
    int deg = g_ideg[n];
    float2 a[4];
    #pragma unroll
    for (int j = 0; j < 4; j++) a[j] = make_float2(0.f, 0.f);

    int i = 0;
    for (; i + 7 < deg; i += 8) {
        int s[8];
        #pragma unroll
        for (int t = 0; t < 8; t++) s[t] = __ldg(g_esrc + beg + i + t);
        uint4 v[8];
        #pragma unroll
        for (int t = 0; t < 8; t++)
            v[t] = __ldg((const uint4*)(g_z1 + (size_t)s[t] * (NB * HIDD)) + lane);
        #pragma unroll
        for (int j = 0; j < 4; j++) {
            const __half2 w0 = *((const __half2*)&v[0].x + 0), w1 = *((const __half2*)&v[1].x + 0);
            // index word j of each uint4
            __half2 x0 = __hadd2(((const __half2*)&v[0])[j], ((const __half2*)&v[1])[j]);
            __half2 x1 = __hadd2(((const __half2*)&v[2])[j], ((const __half2*)&v[3])[j]);
            __half2 x2 = __hadd2(((const __half2*)&v[4])[j], ((const __half2*)&v[5])[j]);
            __half2 x3 = __hadd2(((const __half2*)&v[6])[j], ((const __half2*)&v[7])[j]);
            __half2 y0 = __hadd2(x0, x1);
            __half2 y1 = __hadd2(x2, x3);
            float2 f = __half22float2(__hadd2(y0, y1));
            a[j].x += f.x;
            a[j].y += f.y;
            (void)w0; (void)w1;
        }
    }
    for (; i + 3 < deg; i += 4) {
        int s0 = __ldg(g_esrc + beg + i);
        int s1 = __ldg(g_esrc + beg + i + 1);
        int s2 = __ldg(g_esrc + beg + i + 2);
        int s3 = __ldg(g_esrc + beg + i + 3);
        uint4 v0 = __ldg((const uint4*)(g_z1 + (size_t)s0 * (NB * HIDD)) + lane);
        uint4 v1 = __ldg((const uint4*)(g_z1 + (size_t)s1 * (NB * HIDD)) + lane);
        uint4 v2 = __ldg((const uint4*)(g_z1 + (size_t)s2 * (NB * HIDD)) + lane);
        uint4 v3 = __ldg((const uint4*)(g_z1 + (size_t)s3 * (NB * HIDD)) + lane);
        #pragma unroll
        for (int j = 0; j < 4; j++) {
            __half2 h01 = __hadd2(((const __half2*)&v0)[j], ((const __half2*)&v1)[j]);
            __half2 h23 = __hadd2(((const __half2*)&v2)[j], ((const __half2*)&v3)[j]);
            float2 f = __half22float2(__hadd2(h01, h23));
            a[j].x += f.x;
            a[j].y += f.y;
        }
    }
    for (; i < deg; i++) {
        int s0 = __ldg(g_esrc + beg + i);
        uint4 v0 = __ldg((const uint4*)(g_z1 + (size_t)s0 * (NB * HIDD)) + lane);
        #pragma unroll
        for (int j = 0; j < 4; j++) {
            float2 f0 = __half22float2(((const __half2*)&v0)[j]);
            a[j].x += f0.x;
            a[j].y += f0.y;
        }
    }
    float* ap = g_agg1 + (size_t)n * (NB * HIDD) + lane * 8;
    *(float4*)(ap)     = make_float4(a[0].x, a[0].y, a[1].x, a[1].y);
    *(float4*)(ap + 4) = make_float4(a[2].x, a[2].y, a[3].x, a[3].y);
}

// ================= tensor-core GEMM 2 (B packed for LDS.128) =================
__global__ void __launch_bounds__(256) k_gemm2(const float* __restrict__ W2,
                                               const float* __restrict__ b1) {
    __shared__ u32 sA[128 * 64];        // 32 KB
    __shared__ u32 sBf[8 * 2 * 32 * 4]; // 8 KB
    int tid = threadIdx.x;
    int lane = tid & 31;
    int w = tid >> 5;
    int row0 = blockIdx.x * 128;

    #pragma unroll
    for (int idx = tid; idx < HIDD * OUTD; idx += 256) {
        int k = idx >> 5, n = idx & 31;
        int kt = k >> 3, kr = k & 7;
        int i = kr >> 2;
        int fl = ((n & 7) << 2) | (kr & 3);
        int nt = n >> 3;
        int p = nt >> 1;
        int j = ((nt & 1) << 1) | i;
        sBf[(((kt * 2 + p) * 32) + fl) * 4 + j] = tf32(__ldg(W2 + idx));
    }
    #pragma unroll
    for (int it = 0; it < 8; it++) {
        int idx = tid + it * 256;
        int r_l = idx >> 4;
        int kq  = idx & 15;
        int row = row0 + r_l;
        float4 v = make_float4(0.f, 0.f, 0.f, 0.f);
        if (row < NROWS) {
            float dn = g_dnorm[row >> 2];
            float4 a = *(const float4*)(g_agg1 + (size_t)row * HIDD + kq * 4);
            const float4 bb = __ldg((const float4*)(b1 + kq * 4));
            v.x = fmaxf(a.x * dn + bb.x, 0.f);
            v.y = fmaxf(a.y * dn + bb.y, 0.f);
            v.z = fmaxf(a.z * dn + bb.z, 0.f);
            v.w = fmaxf(a.w * dn + bb.w, 0.f);
        }
        int cc = (kq * 4) ^ ((r_l & 7) * 4);
        uint4 sv = make_uint4(tf32(v.x), tf32(v.y), tf32(v.z), tf32(v.w));
        *(uint4*)&sA[r_l * 64 + cc] = sv;
    }
    __syncthreads();

    float acc[4][4];
    #pragma unroll
    for (int nt = 0; nt < 4; nt++)
        #pragma unroll
        for (int j = 0; j < 4; j++) acc[nt][j] = 0.f;

    int rloc = w * 16 + (lane >> 2);
    const u32* rowp = sA + rloc * 64;
    const uint4* bq = (const uint4*)sBf;
    #pragma unroll
    for (int kt = 0; kt < 8; kt++) {
        int col0 = (kt * 8 + (lane & 3)) ^ (((lane >> 2) & 7) * 4);
        u32 a0 = rowp[col0];
        u32 a2 = rowp[col0 ^ 4];
        u32 a1 = rowp[col0 + 8 * 64];
        u32 a3 = rowp[(col0 ^ 4) + 8 * 64];
        #pragma unroll
        for (int p = 0; p < 2; p++) {
            uint4 b = bq[(kt * 2 + p) * 32 + lane];
            mma_tf32(acc[2 * p],     a0, a1, a2, a3, b.x, b.y);
            mma_tf32(acc[2 * p + 1], a0, a1, a2, a3, b.z, b.w);
        }
    }

    int r0 = row0 + rloc;
    int r1 = r0 + 8;
    int colb = (lane & 3) * 2;
    if (r0 < NROWS) {
        float sc = g_snorm[r0 >> 2];
        #pragma unroll
        for (int nt = 0; nt < 4; nt++) {
            __half2 hv = __floats2half2_rn(sc * acc[nt][0], sc * acc[nt][1]);
            *(__half2*)(g_z2 + (size_t)r0 * OUTD + nt * 8 + colb) = hv;
        }
    }
    if (r1 < NROWS) {
        float sc = g_snorm[r1 >> 2];
        #pragma unroll
        for (int nt = 0; nt < 4; nt++) {
            __half2 hv = __floats2half2_rn(sc * acc[nt][2], sc * acc[nt][3]);
            *(__half2*)(g_z2 + (size_t)r1 * OUTD + nt * 8 + colb) = hv;
        }
    }
}

// ---------------- gather layer 2 + epilogue (fp16 tree) + degree re-zero ----------------
__global__ void __launch_bounds__(256) k_agg2(const float* __restrict__ b2,
                                              float* __restrict__ out) {
    int lane = threadIdx.x & 31;
    int n = blockIdx.x * 8 + (threadIdx.x >> 5);
    if (n >= NN) return;
    int beg = g_coff[n];
    int deg = g_ideg[n];
    float2 a0 = make_float2(0.f, 0.f), a1 = a0;

    int i = 0;
    for (; i + 3 < deg; i += 4) {
        int s0 = __ldg(g_esrc + beg + i);
        int s1 = __ldg(g_esrc + beg + i + 1);
        int s2 = __ldg(g_esrc + beg + i + 2);
        int s3 = __ldg(g_esrc + beg + i + 3);
        uint2 v0 = __ldg((const uint2*)(g_z2 + (size_t)s0 * (NB * OUTD)) + lane);
        uint2 v1 = __ldg((const uint2*)(g_z2 + (size_t)s1 * (NB * OUTD)) + lane);
        uint2 v2 = __ldg((const uint2*)(g_z2 + (size_t)s2 * (NB * OUTD)) + lane);
        uint2 v3 = __ldg((const uint2*)(g_z2 + (size_t)s3 * (NB * OUTD)) + lane);
        {
            __half2 h01 = __hadd2(*(const __half2*)&v0.x, *(const __half2*)&v1.x);
            __half2 h23 = __hadd2(*(const __half2*)&v2.x, *(const __half2*)&v3.x);
            float2 f = __half22float2(__hadd2(h01, h23));
            a0.x += f.x; a0.y += f.y;
        }
        {
            __half2 h01 = __hadd2(*(const __half2*)&v0.y, *(const __half2*)&v1.y);
            __half2 h23 = __hadd2(*(const __half2*)&v2.y, *(const __half2*)&v3.y);
            float2 f = __half22float2(__hadd2(h01, h23));
            a1.x += f.x; a1.y += f.y;
        }
    }
    for (; i < deg; i++) {
        int s0 = __ldg(g_esrc + beg + i);
        uint2 v0 = __ldg((const uint2*)(g_z2 + (size_t)s0 * (NB * OUTD)) + lane);
        float2 f;
        f = __half22float2(*(const __half2*)&v0.x); a0.x += f.x; a0.y += f.y;
        f = __half22float2(*(const __half2*)&v0.y); a1.x += f.x; a1.y += f.y;
    }

    float dn = g_dnorm[n];
    int b = lane >> 3, fq = lane & 7;
    float4 bb = __ldg((const float4*)(b2 + fq * 4));
    float4 o = make_float4(a0.x * dn + bb.x, a0.y * dn + bb.y,
                           a1.x * dn + bb.z, a1.y * dn + bb.w);
    *(float4*)(out + ((size_t)b * NN + n) * OUTD + fq * 4) = o;

    if (lane == 0) { g_odeg[n] = 0; g_ideg[n] = 0; }
}

// ---------------- launch ----------------

extern "C" void kernel_launch(void* const* d_in, const int* in_sizes, int n_in,
                              void* d_out, int out_size) {
    const float* h  = (const float*)d_in[0];
    const float* W1 = (const float*)d_in[1];
    const float* b1 = (const float*)d_in[2];
    const float* W2 = (const float*)d_in[3];
    const float* b2 = (const float*)d_in[4];
    const int* src  = (const int*)d_in[5];
    const int* dst  = (const int*)d_in[6];
    float* out = (float*)d_out;

    k_deg<<<2048, 256>>>(src, dst);
    k_scanall<<<N_SCAN_BLKS, SCAN_BLK>>>();
    k_fill<<<2048, 256>>>(src, dst);
    k_gemm1<<<(NROWS + 127) / 128, 256>>>(h, W1);
    k_agg1<<<(NN + 7) / 8, 256>>>();
    k_gemm2<<<(NROWS + 127) / 128, 256>>>(W2, b1);
    k_agg2<<<(NN + 7) / 8, 256>>>(b2, out);
}

// round 16
// speedup vs baseline: 1.1621x; 1.1621x over previous
#include <cuda_runtime.h>
#include <cuda_fp16.h>

#define NN   50000
#define NE   800000
#define NB   4
#define IND  64
#define HIDD 64
#define OUTD 32
#define NROWS (NN * NB)          // 200000

typedef unsigned long long u64;
typedef unsigned int u32;

// ---------------- scratch (static device globals; zero-init at load) ----------------
__device__ __align__(16) __half g_z1[(size_t)NN * NB * HIDD];  // fp16 (h@W1)*snorm, node-major [q=n*4+b][64]
__device__ __align__(16) __half g_z2[(size_t)NN * NB * OUTD];  // fp16 snorm*(relu(agg*dn+b1)@W2)
__device__ float g_snorm[NN];
__device__ float g_dnorm[NN];
__device__ int   g_odeg[NN];     // zeroed at tail of k_agg2 each call
__device__ int   g_ideg[NN];     // ditto
__device__ int   g_coff[NN];
__device__ int   g_cur [NN];
__device__ int   g_esrc[NE];
__device__ volatile u64 g_pub[128];   // scan block publications: bit63=ready | total

// ---------------- tf32 helpers ----------------
__device__ __forceinline__ u32 tf32(float f) {
    u32 r; asm("cvt.rna.tf32.f32 %0, %1;" : "=r"(r) : "f"(f)); return r;
}
__device__ __forceinline__ void mma_tf32(float* c, u32 a0, u32 a1, u32 a2, u32 a3,
                                         u32 b0, u32 b1) {
    asm volatile(
        "mma.sync.aligned.m16n8k8.row.col.f32.tf32.tf32.f32 "
        "{%0,%1,%2,%3}, {%4,%5,%6,%7}, {%8,%9}, {%0,%1,%2,%3};"
        : "+f"(c[0]), "+f"(c[1]), "+f"(c[2]), "+f"(c[3])
        : "r"(a0), "r"(a1), "r"(a2), "r"(a3), "r"(b0), "r"(b1));
}

// ---------------- degree count (+ reset scan publications) ----------------
__global__ void k_deg(const int* __restrict__ src, const int* __restrict__ dst) {
    int i = blockIdx.x * blockDim.x + threadIdx.x;
    if (blockIdx.x == 0 && threadIdx.x < 128) g_pub[threadIdx.x] = 0ull;
    int stride = gridDim.x * blockDim.x;
    for (int e = i; e < NE; e += stride) {
        atomicAdd(&g_odeg[__ldg(src + e)], 1);
        atomicAdd(&g_ideg[__ldg(dst + e)], 1);
    }
}

// ---------------- single-pass scan + norms ----------------
#define SCAN_BLK 512
#define N_SCAN_BLKS ((NN + SCAN_BLK - 1) / SCAN_BLK)   // 98

__global__ void __launch_bounds__(SCAN_BLK) k_scanall() {
    __shared__ int ws[16];
    __shared__ int s_base;
    int t = threadIdx.x;
    int bid = blockIdx.x;
    int g = bid * SCAN_BLK + t;
    int ideg = (g < NN) ? g_ideg[g] : 0;

    int x = ideg;
    #pragma unroll
    for (int o = 1; o < 32; o <<= 1) {
        int y = __shfl_up_sync(0xffffffffu, x, o);
        if ((t & 31) >= o) x += y;
    }
    if ((t & 31) == 31) ws[t >> 5] = x;
    __syncthreads();
    if (t < 32) {
        int s = (t < 16) ? ws[t] : 0;
        #pragma unroll
        for (int o = 1; o < 16; o <<= 1) {
            int y = __shfl_up_sync(0xffffffffu, s, o);
            if (t >= o) s += y;
        }
        if (t < 16) ws[t] = s;
    }
    __syncthreads();
    int wbase = (t >> 5) ? ws[(t >> 5) - 1] : 0;
    int incl = x + wbase;

    if (t == SCAN_BLK - 1)
        g_pub[bid] = (1ull << 63) | (u64)(unsigned)incl;

    if (t < 32) {
        int sum = 0;
        for (int j = t; j < bid; j += 32) {
            u64 p;
            do { p = g_pub[j]; } while (!(p >> 63));
            sum += (int)(unsigned)p;
        }
        #pragma unroll
        for (int o = 16; o > 0; o >>= 1)
            sum += __shfl_xor_sync(0xffffffffu, sum, o);
        if (t == 0) s_base = sum;
    }
    __syncthreads();

    if (g < NN) {
        int ex = s_base + incl - ideg;
        g_coff[g] = ex;
        g_cur[g]  = ex;
        g_snorm[g] = rsqrtf((float)max(g_odeg[g], 1));
        g_dnorm[g] = rsqrtf((float)max(ideg, 1));
    }
}

__global__ void k_fill(const int* __restrict__ src, const int* __restrict__ dst) {
    int i = blockIdx.x * blockDim.x + threadIdx.x;
    int stride = gridDim.x * blockDim.x;
    for (int e = i; e < NE; e += stride) {
        int d = __ldg(dst + e);
        int pos = atomicAdd(&g_cur[d], 1);
        g_esrc[pos] = __ldg(src + e);
    }
}

// ================= tensor-core GEMM 1 (R13 form) =================
__global__ void __launch_bounds__(256) k_gemm1(const float* __restrict__ h,
                                               const float* __restrict__ W1) {
    __shared__ u32 sA[128 * 64];      // 32 KB
    __shared__ u32 sBf[8 * 8 * 32 * 2]; // 16 KB
    int tid = threadIdx.x;
    int lane = tid & 31;
    int w = tid >> 5;
    int row0 = blockIdx.x * 128;

    #pragma unroll
    for (int idx = tid; idx < IND * HIDD; idx += 256) {
        int k = idx >> 6, n = idx & 63;
        int kt = k >> 3, kr = k & 7;
        int i = kr >> 2;
        int fl = ((n & 7) << 2) | (kr & 3);
        int nt = n >> 3;
        sBf[(((kt * 8 + nt) * 32) + fl) * 2 + i] = tf32(__ldg(W1 + idx));
    }
    #pragma unroll
    for (int it = 0; it < 8; it++) {
        int idx = tid + it * 256;        // 0..2047
        int r_l = idx >> 4;              // 0..127
        int kq  = idx & 15;              // float4 col
        int row = row0 + r_l;
        float4 v = make_float4(0.f, 0.f, 0.f, 0.f);
        if (row < NROWS) v = __ldg((const float4*)(h + (size_t)row * IND + kq * 4));
        int cc = (kq * 4) ^ ((r_l & 7) * 4);
        uint4 sv = make_uint4(tf32(v.x), tf32(v.y), tf32(v.z), tf32(v.w));
        *(uint4*)&sA[r_l * 64 + cc] = sv;
    }
    __syncthreads();

    float acc[8][4];
    #pragma unroll
    for (int nt = 0; nt < 8; nt++)
        #pragma unroll
        for (int j = 0; j < 4; j++) acc[nt][j] = 0.f;

    int rloc = w * 16 + (lane >> 2);
    const u32* rowp = sA + rloc * 64;
    #pragma unroll
    for (int kt = 0; kt < 8; kt++) {
        int col0 = (kt * 8 + (lane & 3)) ^ (((lane >> 2) & 7) * 4);
        u32 a0 = rowp[col0];
        u32 a2 = rowp[col0 ^ 4];
        u32 a1 = rowp[col0 + 8 * 64];
        u32 a3 = rowp[(col0 ^ 4) + 8 * 64];
        #pragma unroll
        for (int nt = 0; nt < 8; nt++) {
            uint2 b = *(const uint2*)&sBf[(((kt * 8 + nt) * 32) + lane) * 2];
            mma_tf32(acc[nt], a0, a1, a2, a3, b.x, b.y);
        }
    }

    int r0 = row0 + rloc;
    int r1 = r0 + 8;
    int colb = (lane & 3) * 2;
    if (r0 < NROWS) {
        int b_ = r0 / NN, n_ = r0 - b_ * NN;
        float sc = g_snorm[n_];
        size_t base = ((size_t)n_ * NB + b_) * HIDD;
        #pragma unroll
        for (int nt = 0; nt < 8; nt++) {
            __half2 hv = __floats2half2_rn(sc * acc[nt][0], sc * acc[nt][1]);
            *(__half2*)(g_z1 + base + nt * 8 + colb) = hv;
        }
    }
    if (r1 < NROWS) {
        int b_ = r1 / NN, n_ = r1 - b_ * NN;
        float sc = g_snorm[n_];
        size_t base = ((size_t)n_ * NB + b_) * HIDD;
        #pragma unroll
        for (int nt = 0; nt < 8; nt++) {
            __half2 hv = __floats2half2_rn(sc * acc[nt][2], sc * acc[nt][3]);
            *(__half2*)(g_z1 + base + nt * 8 + colb) = hv;
        }
    }
}

// ================= FUSED gather-1 + tensor GEMM 2 =================
// Block covers rows [row0, row0+128) = nodes [row0/4, row0/4+32).
// Phase A: each warp gathers 4 nodes (R13 agg1 pattern, fp16 tree), applies
//          relu(agg*dnorm + b1), converts to tf32, writes swizzled sA rows.
// Phase B: R13 gemm2 MMA mainloop + snorm/fp16 epilogue -> g_z2.
__global__ void __launch_bounds__(256) k_agg_gemm2(const float* __restrict__ W2,
                                                   const float* __restrict__ b1) {
    __shared__ u32 sA[128 * 64];        // 32 KB
    __shared__ u32 sBf[8 * 4 * 32 * 2]; // 8 KB
    int tid = threadIdx.x;
    int lane = tid & 31;
    int w = tid >> 5;
    int row0 = blockIdx.x * 128;
    int node0 = blockIdx.x * 32;

    // stage W2 fragments (R13 layout)
    #pragma unroll
    for (int idx = tid; idx < HIDD * OUTD; idx += 256) {
        int k = idx >> 5, n = idx & 31;
        int kt = k >> 3, kr = k & 7;
        int i = kr >> 2;
        int fl = ((n & 7) << 2) | (kr & 3);
        int nt = n >> 3;
        sBf[(((kt * 4 + nt) * 32) + fl) * 2 + i] = tf32(__ldg(W2 + idx));
    }

    // per-lane constants: k columns owned = (lane&7)*8 .. +7 ; b = lane>>3
    int kbase = (lane & 7) * 8;
    float4 bb0 = __ldg((const float4*)(b1 + kbase));
    float4 bb1 = __ldg((const float4*)(b1 + kbase + 4));

    // ---- Phase A: gather 4 nodes per warp into sA ----
    for (int nl = 0; nl < 4; nl++) {
        int n = node0 + w * 4 + nl;
        float2 a[4];
        #pragma unroll
        for (int j = 0; j < 4; j++) a[j] = make_float2(0.f, 0.f);
        float dn = 0.f;
        if (n < NN) {
            int beg = g_coff[n];
            int deg = g_ideg[n];
            dn = g_dnorm[n];
            int i = 0;
            for (; i + 3 < deg; i += 4) {
                int s0 = __ldg(g_esrc + beg + i);
                int s1 = __ldg(g_esrc + beg + i + 1);
                int s2 = __ldg(g_esrc + beg + i + 2);
                int s3 = __ldg(g_esrc + beg + i + 3);
                uint4 v0 = __ldg((const uint4*)(g_z1 + (size_t)s0 * (NB * HIDD)) + lane);
                uint4 v1 = __ldg((const uint4*)(g_z1 + (size_t)s1 * (NB * HIDD)) + lane);
                uint4 v2 = __ldg((const uint4*)(g_z1 + (size_t)s2 * (NB * HIDD)) + lane);
                uint4 v3 = __ldg((const uint4*)(g_z1 + (size_t)s3 * (NB * HIDD)) + lane);
                #pragma unroll
                for (int j = 0; j < 4; j++) {
                    __half2 h01 = __hadd2(((const __half2*)&v0)[j], ((const __half2*)&v1)[j]);
                    __half2 h23 = __hadd2(((const __half2*)&v2)[j], ((const __half2*)&v3)[j]);
                    float2 f = __half22float2(__hadd2(h01, h23));
                    a[j].x += f.x;
                    a[j].y += f.y;
                }
            }
            for (; i < deg; i++) {
                int s0 = __ldg(g_esrc + beg + i);
                uint4 v0 = __ldg((const uint4*)(g_z1 + (size_t)s0 * (NB * HIDD)) + lane);
                #pragma unroll
                for (int j = 0; j < 4; j++) {
                    float2 f0 = __half22float2(((const __half2*)&v0)[j]);
                    a[j].x += f0.x;
                    a[j].y += f0.y;
                }
            }
        }
        // relu(agg*dn + b1) -> tf32 -> swizzled sA rows
        // lane element e = lane*8 + t maps to (b = lane>>3, k = kbase + t)
        float y0 = fmaxf(a[0].x * dn + bb0.x, 0.f);
        float y1 = fmaxf(a[0].y * dn + bb0.y, 0.f);
        float y2 = fmaxf(a[1].x * dn + bb0.z, 0.f);
        float y3 = fmaxf(a[1].y * dn + bb0.w, 0.f);
        float y4 = fmaxf(a[2].x * dn + bb1.x, 0.f);
        float y5 = fmaxf(a[2].y * dn + bb1.y, 0.f);
        float y6 = fmaxf(a[3].x * dn + bb1.z, 0.f);
        float y7 = fmaxf(a[3].y * dn + bb1.w, 0.f);

        int r_l = (w * 4 + nl) * 4 + (lane >> 3);   // local row (q-space)
        int kq0 = (lane & 7) * 2;                   // float4 group index
        int sw = (r_l & 7) * 4;
        uint4 s0v = make_uint4(tf32(y0), tf32(y1), tf32(y2), tf32(y3));
        uint4 s1v = make_uint4(tf32(y4), tf32(y5), tf32(y6), tf32(y7));
        *(uint4*)&sA[r_l * 64 + ((kq0 * 4) ^ sw)] = s0v;
        *(uint4*)&sA[r_l * 64 + (((kq0 + 1) * 4) ^ sw)] = s1v;
    }
    __syncthreads();

    // ---- Phase B: MMA mainloop + epilogue ----
    float acc[4][4];
    #pragma unroll
    for (int nt = 0; nt < 4; nt++)
        #pragma unroll
        for (int j = 0; j < 4; j++) acc[nt][j] = 0.f;

    int rloc = w * 16 + (lane >> 2);
    const u32* rowp = sA + rloc * 64;
    #pragma unroll
    for (int kt = 0; kt < 8; kt++) {
        int col0 = (kt * 8 + (lane & 3)) ^ (((lane >> 2) & 7) * 4);
        u32 a0 = rowp[col0];
        u32 a2 = rowp[col0 ^ 4];
        u32 a1 = rowp[col0 + 8 * 64];
        u32 a3 = rowp[(col0 ^ 4) + 8 * 64];
        #pragma unroll
        for (int nt = 0; nt < 4; nt++) {
            uint2 b = *(const uint2*)&sBf[(((kt * 4 + nt) * 32) + lane) * 2];
            mma_tf32(acc[nt], a0, a1, a2, a3, b.x, b.y);
        }
    }

    int r0 = row0 + rloc;
    int r1 = r0 + 8;
    int colb = (lane & 3) * 2;
    if (r0 < NROWS) {
        float sc = g_snorm[r0 >> 2];
        #pragma unroll
        for (int nt = 0; nt < 4; nt++) {
            __half2 hv = __floats2half2_rn(sc * acc[nt][0], sc * acc[nt][1]);
            *(__half2*)(g_z2 + (size_t)r0 * OUTD + nt * 8 + colb) = hv;
        }
    }
    if (r1 < NROWS) {
        float sc = g_snorm[r1 >> 2];
        #pragma unroll
        for (int nt = 0; nt < 4; nt++) {
            __half2 hv = __floats2half2_rn(sc * acc[nt][2], sc * acc[nt][3]);
            *(__half2*)(g_z2 + (size_t)r1 * OUTD + nt * 8 + colb) = hv;
        }
    }
}

// ---------------- gather layer 2 + epilogue (fp16 tree) + degree re-zero ----------------
__global__ void __launch_bounds__(256) k_agg2(const float* __restrict__ b2,
                                              float* __restrict__ out) {
    int lane = threadIdx.x & 31;
    int n = blockIdx.x * 8 + (threadIdx.x >> 5);
    if (n >= NN) return;
    int beg = g_coff[n];
    int deg = g_ideg[n];
    float2 a0 = make_float2(0.f, 0.f), a1 = a0;

    int i = 0;
    for (; i + 3 < deg; i += 4) {
        int s0 = __ldg(g_esrc + beg + i);
        int s1 = __ldg(g_esrc + beg + i + 1);
        int s2 = __ldg(g_esrc + beg + i + 2);
        int s3 = __ldg(g_esrc + beg + i + 3);
        uint2 v0 = __ldg((const uint2*)(g_z2 + (size_t)s0 * (NB * OUTD)) + lane);
        uint2 v1 = __ldg((const uint2*)(g_z2 + (size_t)s1 * (NB * OUTD)) + lane);
        uint2 v2 = __ldg((const uint2*)(g_z2 + (size_t)s2 * (NB * OUTD)) + lane);
        uint2 v3 = __ldg((const uint2*)(g_z2 + (size_t)s3 * (NB * OUTD)) + lane);
        {
            __half2 h01 = __hadd2(*(const __half2*)&v0.x, *(const __half2*)&v1.x);
            __half2 h23 = __hadd2(*(const __half2*)&v2.x, *(const __half2*)&v3.x);
            float2 f = __half22float2(__hadd2(h01, h23));
            a0.x += f.x; a0.y += f.y;
        }
        {
            __half2 h01 = __hadd2(*(const __half2*)&v0.y, *(const __half2*)&v1.y);
            __half2 h23 = __hadd2(*(const __half2*)&v2.y, *(const __half2*)&v3.y);
            float2 f = __half22float2(__hadd2(h01, h23));
            a1.x += f.x; a1.y += f.y;
        }
    }
    for (; i < deg; i++) {
        int s0 = __ldg(g_esrc + beg + i);
        uint2 v0 = __ldg((const uint2*)(g_z2 + (size_t)s0 * (NB * OUTD)) + lane);
        float2 f;
        f = __half22float2(*(const __half2*)&v0.x); a0.x += f.x; a0.y += f.y;
        f = __half22float2(*(const __half2*)&v0.y); a1.x += f.x; a1.y += f.y;
    }

    float dn = g_dnorm[n];
    int b = lane >> 3, fq = lane & 7;
    float4 bb = __ldg((const float4*)(b2 + fq * 4));
    float4 o = make_float4(a0.x * dn + bb.x, a0.y * dn + bb.y,
                           a1.x * dn + bb.z, a1.y * dn + bb.w);
    *(float4*)(out + ((size_t)b * NN + n) * OUTD + fq * 4) = o;

    if (lane == 0) { g_odeg[n] = 0; g_ideg[n] = 0; }
}

// ---------------- launch ----------------

extern "C" void kernel_launch(void* const* d_in, const int* in_sizes, int n_in,
                              void* d_out, int out_size) {
    const float* h  = (const float*)d_in[0];
    const float* W1 = (const float*)d_in[1];
    const float* b1 = (const float*)d_in[2];
    const float* W2 = (const float*)d_in[3];
    const float* b2 = (const float*)d_in[4];
    const int* src  = (const int*)d_in[5];
    const int* dst  = (const int*)d_in[6];
    float* out = (float*)d_out;

    k_deg<<<2048, 256>>>(src, dst);
    k_scanall<<<N_SCAN_BLKS, SCAN_BLK>>>();
    k_fill<<<2048, 256>>>(src, dst);
    k_gemm1<<<(NROWS + 127) / 128, 256>>>(h, W1);
    k_agg_gemm2<<<(NROWS + 127) / 128, 256>>>(W2, b1);
    k_agg2<<<(NN + 7) / 8, 256>>>(b2, out);
}